// round 2
// baseline (speedup 1.0000x reference)
#include <cuda_runtime.h>
#include <cuda_bf16.h>

// ---------------------------------------------------------------------------
// MultiHeadAttention: x[8,1024,768] @ W_qkv^T[768,2304] + b -> Q,K,V heads,
// scores = floor(QK^T / 8), softmax, out = attn @ V  -> [8,12,1024,64] fp32.
// Strategy: exact fp32 everywhere (floor() is boundary-sensitive),
// packed f32x2 FMA for 2x fp32 throughput, flash-style attention without
// max-tracking (scores are small integers after floor => exp cannot overflow).
// ---------------------------------------------------------------------------

#define BATCH   8
#define SEQ     1024
#define EMBED   768
#define HEADS   12
#define HD      64
#define QSIZE   (BATCH * HEADS * SEQ * HD)   /* 6291456 */

// Scratch for projected Q,K,V in [B,H,N,D] layout (s=0:Q, 1:K, 2:V)
__device__ float g_qkv[3ULL * QSIZE];

// --------------------------- f32x2 helpers ---------------------------------
__device__ __forceinline__ unsigned long long ffma2(unsigned long long a,
                                                    unsigned long long b,
                                                    unsigned long long c) {
    unsigned long long d;
    asm("fma.rn.f32x2 %0, %1, %2, %3;" : "=l"(d) : "l"(a), "l"(b), "l"(c));
    return d;
}
__device__ __forceinline__ float f2lo(unsigned long long v) {
    return __uint_as_float((unsigned int)(v & 0xffffffffULL));
}
__device__ __forceinline__ float f2hi(unsigned long long v) {
    return __uint_as_float((unsigned int)(v >> 32));
}

// --------------------------- QKV projection GEMM ---------------------------
// C[8192,2304] = X[8192,768] @ W^T + b, scattered into g_qkv [s][b,h,n,d].
// Tiles: BM=64, BN=128, BK=32; 256 threads; 4x8 microtile; f32x2 paired over K.

#define GM_BM 64
#define GM_BN 128
#define GM_BK 32
#define GM_SD 36   /* smem row stride in floats (32 + 4 pad, 16B-multiple) */

__global__ __launch_bounds__(256, 2)
void qkv_gemm_kernel(const float* __restrict__ X,
                     const float* __restrict__ W,
                     const float* __restrict__ bias) {
    __shared__ float Xs[GM_BM][GM_SD];
    __shared__ float Ws[GM_BN][GM_SD];

    const int t  = threadIdx.x;
    const int tx = t & 15;
    const int ty = t >> 4;
    const int m0 = blockIdx.y * GM_BM;
    const int n0 = blockIdx.x * GM_BN;

    unsigned long long acc[4][8];
#pragma unroll
    for (int i = 0; i < 4; i++)
#pragma unroll
        for (int j = 0; j < 8; j++) acc[i][j] = 0ULL;

    for (int k0 = 0; k0 < EMBED; k0 += GM_BK) {
        // Load X tile: 64 rows x 32 k = 512 float4
#pragma unroll
        for (int it = 0; it < 2; it++) {
            int f   = t + 256 * it;
            int row = f >> 3;
            int kq  = f & 7;
            float4 v = *reinterpret_cast<const float4*>(
                X + (size_t)(m0 + row) * EMBED + k0 + kq * 4);
            *reinterpret_cast<float4*>(&Xs[row][kq * 4]) = v;
        }
        // Load W tile: 128 cols x 32 k = 1024 float4 (W row-major [2304,768])
#pragma unroll
        for (int it = 0; it < 4; it++) {
            int f   = t + 256 * it;
            int col = f >> 3;
            int kq  = f & 7;
            float4 v = *reinterpret_cast<const float4*>(
                W + (size_t)(n0 + col) * EMBED + k0 + kq * 4);
            *reinterpret_cast<float4*>(&Ws[col][kq * 4]) = v;
        }
        __syncthreads();

#pragma unroll
        for (int kq = 0; kq < 8; kq++) {
            ulonglong2 a[4];
#pragma unroll
            for (int i = 0; i < 4; i++)
                a[i] = *reinterpret_cast<const ulonglong2*>(&Xs[ty * 4 + i][kq * 4]);
#pragma unroll
            for (int j = 0; j < 8; j++) {
                ulonglong2 b = *reinterpret_cast<const ulonglong2*>(&Ws[tx + 16 * j][kq * 4]);
#pragma unroll
                for (int i = 0; i < 4; i++) {
                    acc[i][j] = ffma2(a[i].x, b.x, acc[i][j]);
                    acc[i][j] = ffma2(a[i].y, b.y, acc[i][j]);
                }
            }
        }
        __syncthreads();
    }

    // Epilogue: add bias, scatter into [s][b,h,n,d]
#pragma unroll
    for (int j = 0; j < 8; j++) {
        int c   = n0 + tx + 16 * j;
        float bv = __ldg(bias + c);
        int s   = c / EMBED;          // 0=Q 1=K 2=V
        int rem = c - s * EMBED;
        int h   = rem >> 6;
        int d   = rem & 63;
#pragma unroll
        for (int i = 0; i < 4; i++) {
            int m = m0 + ty * 4 + i;
            int b = m >> 10;          // batch
            int n = m & 1023;         // seq pos
            float v = f2lo(acc[i][j]) + f2hi(acc[i][j]) + bv;
            g_qkv[(size_t)s * QSIZE +
                  ((size_t)(b * HEADS + h) * SEQ + n) * HD + d] = v;
        }
    }
}

// ------------------------------- Attention ---------------------------------
// Per block: one (b,h) pair, 64 query rows. Loops over 16 KV tiles of 64.
// S = Q K^T (f32x2), s = floor(s/8), p = expf(s) (no max subtraction needed:
// floored scores are small integers, e^s cannot overflow), accumulate
// O += P @ V via smem P tile + transposed V tile, normalize by row sum at end.

#define ATT_SD 68    /* smem row stride in floats (64 + 4 pad) */
#define ATT_SMEM (4 * 64 * ATT_SD * 4)   /* Qs,Ks,Vt,Ps = 69632 B */

__global__ __launch_bounds__(256, 2)
void attention_kernel(float* __restrict__ out) {
    extern __shared__ float sm[];
    float* Qs = sm;                     // [64][68]  Q rows (d contiguous)
    float* Ks = sm + 64 * ATT_SD;       // [64][68]  K rows (d contiguous)
    float* Vt = sm + 2 * 64 * ATT_SD;   // [64][68]  V transposed: [d][c]
    float* Ps = sm + 3 * 64 * ATT_SD;   // [64][68]  P tile: [r][c]

    const int t  = threadIdx.x;
    const int tx = t & 15;
    const int ty = t >> 4;
    const int bh = blockIdx.y;          // 0..95
    const int r0 = blockIdx.x * 64;

    const float* qb = g_qkv + (size_t)bh * SEQ * HD;
    const float* kb = qb + (size_t)QSIZE;
    const float* vb = qb + 2 * (size_t)QSIZE;

    // Load Q tile
#pragma unroll
    for (int it = 0; it < 4; it++) {
        int f  = t + 256 * it;          // 0..1023
        int r  = f >> 4;
        int dq = f & 15;
        float4 v = *reinterpret_cast<const float4*>(qb + (size_t)(r0 + r) * HD + dq * 4);
        *reinterpret_cast<float4*>(&Qs[r * ATT_SD + dq * 4]) = v;
    }

    unsigned long long o2[4][4];
#pragma unroll
    for (int i = 0; i < 4; i++)
#pragma unroll
        for (int j = 0; j < 4; j++) o2[i][j] = 0ULL;
    float lsum[4] = {0.f, 0.f, 0.f, 0.f};

    for (int c0 = 0; c0 < SEQ; c0 += 64) {
        // Load K tile (row-major, d contiguous)
#pragma unroll
        for (int it = 0; it < 4; it++) {
            int f  = t + 256 * it;
            int c  = f >> 4;
            int dq = f & 15;
            float4 v = *reinterpret_cast<const float4*>(kb + (size_t)(c0 + c) * HD + dq * 4);
            *reinterpret_cast<float4*>(&Ks[c * ATT_SD + dq * 4]) = v;
        }
        // Load V tile transposed: Vt[d][c]. Each task = one float4 of a Vt row.
#pragma unroll
        for (int it = 0; it < 4; it++) {
            int task = t + 256 * it;    // 0..1023
            int d  = task & 63;         // lanes -> consecutive d: coalesced gmem
            int c4 = task >> 6;         // 0..15
            float4 v;
            v.x = vb[(size_t)(c0 + c4 * 4 + 0) * HD + d];
            v.y = vb[(size_t)(c0 + c4 * 4 + 1) * HD + d];
            v.z = vb[(size_t)(c0 + c4 * 4 + 2) * HD + d];
            v.w = vb[(size_t)(c0 + c4 * 4 + 3) * HD + d];
            *reinterpret_cast<float4*>(&Vt[d * ATT_SD + c4 * 4]) = v;
        }
        __syncthreads();

        // S tile: 4x4 per thread, f32x2 paired over d
        unsigned long long s2[4][4];
#pragma unroll
        for (int i = 0; i < 4; i++)
#pragma unroll
            for (int j = 0; j < 4; j++) s2[i][j] = 0ULL;

#pragma unroll
        for (int kq = 0; kq < 16; kq++) {
            ulonglong2 a[4];
#pragma unroll
            for (int i = 0; i < 4; i++)
                a[i] = *reinterpret_cast<const ulonglong2*>(&Qs[(ty * 4 + i) * ATT_SD + kq * 4]);
#pragma unroll
            for (int j = 0; j < 4; j++) {
                ulonglong2 b = *reinterpret_cast<const ulonglong2*>(&Ks[(tx + 16 * j) * ATT_SD + kq * 4]);
#pragma unroll
                for (int i = 0; i < 4; i++) {
                    s2[i][j] = ffma2(a[i].x, b.x, s2[i][j]);
                    s2[i][j] = ffma2(a[i].y, b.y, s2[i][j]);
                }
            }
        }

        // floor(s/8), exp, row-sum partials, stage P to smem
#pragma unroll
        for (int j = 0; j < 4; j++) {
            int c = tx + 16 * j;
#pragma unroll
            for (int i = 0; i < 4; i++) {
                float s = f2lo(s2[i][j]) + f2hi(s2[i][j]);
                s = floorf(s * 0.125f);          // exact: /8 then floor
                float p = __expf(s);             // small-int arg, safe & accurate
                lsum[i] += p;
                Ps[(ty * 4 + i) * ATT_SD + c] = p;
            }
        }
        __syncthreads();

        // O += P @ V  (f32x2 paired over c, using transposed V)
#pragma unroll
        for (int cq = 0; cq < 16; cq++) {
            ulonglong2 a[4];
#pragma unroll
            for (int i = 0; i < 4; i++)
                a[i] = *reinterpret_cast<const ulonglong2*>(&Ps[(ty * 4 + i) * ATT_SD + cq * 4]);
#pragma unroll
            for (int j = 0; j < 4; j++) {
                ulonglong2 b = *reinterpret_cast<const ulonglong2*>(&Vt[(tx + 16 * j) * ATT_SD + cq * 4]);
#pragma unroll
                for (int i = 0; i < 4; i++) {
                    o2[i][j] = ffma2(a[i].x, b.x, o2[i][j]);
                    o2[i][j] = ffma2(a[i].y, b.y, o2[i][j]);
                }
            }
        }
        __syncthreads();   // protect Ks/Vt/Ps before next tile
    }

    // Row-sum allreduce across the 16 tx lanes (stays within 16-lane half-warp)
#pragma unroll
    for (int i = 0; i < 4; i++) {
        float v = lsum[i];
        v += __shfl_xor_sync(0xffffffffu, v, 1);
        v += __shfl_xor_sync(0xffffffffu, v, 2);
        v += __shfl_xor_sync(0xffffffffu, v, 4);
        v += __shfl_xor_sync(0xffffffffu, v, 8);
        lsum[i] = 1.0f / v;
    }

    // Write output [B,H,N,D] (coalesced over d within half-warps)
#pragma unroll
    for (int i = 0; i < 4; i++) {
        int r = r0 + ty * 4 + i;
        float inv = lsum[i];
#pragma unroll
        for (int j = 0; j < 4; j++) {
            int d = tx + 16 * j;
            out[((size_t)bh * SEQ + r) * HD + d] =
                (f2lo(o2[i][j]) + f2hi(o2[i][j])) * inv;
        }
    }
}

// ------------------------------- launch ------------------------------------
extern "C" void kernel_launch(void* const* d_in, const int* in_sizes, int n_in,
                              void* d_out, int out_size) {
    const float* x    = (const float*)d_in[0];   // [8,1024,768]
    const float* wqkv = (const float*)d_in[1];   // [2304,768]
    const float* bias = (const float*)d_in[2];   // [2304]
    float* out = (float*)d_out;                  // [8,12,1024,64]

    (void)cudaFuncSetAttribute(attention_kernel,
                               cudaFuncAttributeMaxDynamicSharedMemorySize, ATT_SMEM);

    // QKV projection: grid (2304/128, 8192/64)
    qkv_gemm_kernel<<<dim3(2304 / GM_BN, (BATCH * SEQ) / GM_BM), 256>>>(x, wqkv, bias);

    // Attention: grid (1024/64 row tiles, 96 head-batch pairs)
    attention_kernel<<<dim3(SEQ / 64, BATCH * HEADS), 256, ATT_SMEM>>>(out);
}